// round 9
// baseline (speedup 1.0000x reference)
#include <cuda_runtime.h>
#include <math.h>
#include <stdint.h>
#include <mma.h>

using namespace nvcuda;

#define Bdim 64
#define Tdim 512
#define Idim 256
#define Hdim 512
#define BH   (Bdim*Hdim)   // 32768

// Scratch (device globals: no allocations allowed)
__device__ float g_xw[(size_t)Tdim*Bdim*Hdim];  // 64 MB, [T,B,H] rows m=t*64+b
__device__ float g_h [(size_t)Tdim*Bdim*Hdim];  // 64 MB, [T,B,H]
__device__ int   g_flag[2][8][32][32];          // fallback flags: one 128B line each

__global__ void zero_flags_k() {
    int i = blockIdx.x * blockDim.x + threadIdx.x;
    if (i < 2 * 8 * 32 * 32) ((int*)g_flag)[i] = 0;
}

__device__ __forceinline__ void st_release_gpu(int* p, int v) {
    asm volatile("st.release.gpu.u32 [%0], %1;" :: "l"(p), "r"(v) : "memory");
}
__device__ __forceinline__ int ld_acquire_gpu(const int* p) {
    int v;
    asm volatile("ld.acquire.gpu.u32 %0, [%1];" : "=r"(v) : "l"(p) : "memory");
    return v;
}
__device__ __forceinline__ uint32_t smem_u32(const void* p) {
    uint32_t a;
    asm("{ .reg .u64 t; cvta.to.shared.u64 t, %1; cvt.u32.u64 %0, t; }" : "=r"(a) : "l"(p));
    return a;
}

#define MBARRIER_INIT(addr, cnt) \
    asm volatile("mbarrier.init.shared.b64 [%0], %1;" :: "r"(addr), "r"(cnt) : "memory")

// Cluster-scope acquire wait on phase parity (HW-sleep try_wait loop)
#define MBAR_WAIT_CL(addr, par) do { \
    uint32_t _m = (addr), _p = (par), _d = 0; \
    do { \
        asm volatile("{\n\t.reg .pred p;\n\t" \
            "mbarrier.try_wait.parity.acquire.cluster.shared::cta.b64 p, [%1], %2, 0x989680;\n\t" \
            "selp.b32 %0, 1, 0, p;\n\t}" : "=r"(_d) : "r"(_m), "r"(_p) : "memory"); \
    } while (!_d); \
} while (0)

// ---------------------------------------------------------------------------
// 3xTF32 tensor-core projection GEMM (near-fp32 accuracy).
// g_xw[m][n] = sum_k A[m][k] * W[n][k] + b1[n] + b2[n]
// v = hi + lo (hi = tf32-rounded); C += hi*hi + hi*lo + lo*hi.
// CTA tile: M=128, N=64, K chunked by 32. 8 warps, each 32x32 (2x2 wmma 16x16x8).
// FIRST: A = x with layout [B,T,I]  (row m=t*64+b -> offset (b*T+t)*KD)
// else : A = g_h with row-major rows m (offset m*KD)
// ---------------------------------------------------------------------------
#define LDA 40                       // 32 + 8 skew
#define A_FL (128 * LDA)
#define B_FL (64 * LDA)
#define TOT_FL (2 * (A_FL + B_FL))   // 15360 floats = 61440 B
#define LDC 72                       // 64 + 8 skew

template<int KD, bool FIRST>
__global__ __launch_bounds__(256, 2) void proj_tc(
    const float* __restrict__ xin, const float* __restrict__ W,
    const float* __restrict__ b1,  const float* __restrict__ b2)
{
    extern __shared__ float s[];     // [A_hi | A_lo | B_hi | B_lo]; reused as C
    float* As_hi = s;
    float* As_lo = s + A_FL;
    float* Bs_hi = s + 2 * A_FL;
    float* Bs_lo = s + 2 * A_FL + B_FL;
    __shared__ float biasS[64];

    const float* __restrict__ A = FIRST ? xin : g_h;
    const int tid = threadIdx.x;
    const int wid = tid >> 5;
    const int n0 = blockIdx.x * 64;
    const int m0 = blockIdx.y * 128;
    const int wm = wid & 3;
    const int wn = wid >> 2;

    if (tid < 64) biasS[tid] = b1[n0 + tid] + b2[n0 + tid];

    int a_row[4], a_col[4];
    #pragma unroll
    for (int i = 0; i < 4; i++) {
        int idx = tid + i * 256;
        a_row[i] = idx >> 3;
        a_col[i] = (idx & 7) * 4;
    }
    int b_row[2], b_col[2];
    #pragma unroll
    for (int i = 0; i < 2; i++) {
        int idx = tid + i * 256;
        b_row[i] = idx >> 3;
        b_col[i] = (idx & 7) * 4;
    }

    size_t a_off[4];
    #pragma unroll
    for (int i = 0; i < 4; i++) {
        int m = m0 + a_row[i];
        a_off[i] = FIRST ? ((size_t)(m & 63) * Tdim + (m >> 6)) * KD
                         : (size_t)m * KD;
    }
    size_t b_off[2];
    #pragma unroll
    for (int i = 0; i < 2; i++)
        b_off[i] = (size_t)(n0 + b_row[i]) * KD;

    wmma::fragment<wmma::accumulator, 16, 16, 8, float> cf[2][2];
    #pragma unroll
    for (int i = 0; i < 2; i++)
        #pragma unroll
        for (int j = 0; j < 2; j++)
            wmma::fill_fragment(cf[i][j], 0.0f);

    float4 pa[4], pb[2];
    #pragma unroll
    for (int i = 0; i < 4; i++)
        pa[i] = *reinterpret_cast<const float4*>(A + a_off[i] + a_col[i]);
    #pragma unroll
    for (int i = 0; i < 2; i++)
        pb[i] = *reinterpret_cast<const float4*>(W + b_off[i] + b_col[i]);

    const int KT = KD / 32;
    for (int kt = 0; kt < KT; ++kt) {
        #pragma unroll
        for (int i = 0; i < 4; i++) {
            int o = a_row[i] * LDA + a_col[i];
            float hx = wmma::__float_to_tf32(pa[i].x);
            float hy = wmma::__float_to_tf32(pa[i].y);
            float hz = wmma::__float_to_tf32(pa[i].z);
            float hw = wmma::__float_to_tf32(pa[i].w);
            As_hi[o+0] = hx; As_hi[o+1] = hy; As_hi[o+2] = hz; As_hi[o+3] = hw;
            As_lo[o+0] = pa[i].x - hx; As_lo[o+1] = pa[i].y - hy;
            As_lo[o+2] = pa[i].z - hz; As_lo[o+3] = pa[i].w - hw;
        }
        #pragma unroll
        for (int i = 0; i < 2; i++) {
            int o = b_row[i] * LDA + b_col[i];
            float hx = wmma::__float_to_tf32(pb[i].x);
            float hy = wmma::__float_to_tf32(pb[i].y);
            float hz = wmma::__float_to_tf32(pb[i].z);
            float hw = wmma::__float_to_tf32(pb[i].w);
            Bs_hi[o+0] = hx; Bs_hi[o+1] = hy; Bs_hi[o+2] = hz; Bs_hi[o+3] = hw;
            Bs_lo[o+0] = pb[i].x - hx; Bs_lo[o+1] = pb[i].y - hy;
            Bs_lo[o+2] = pb[i].z - hz; Bs_lo[o+3] = pb[i].w - hw;
        }
        __syncthreads();

        if (kt + 1 < KT) {
            int k0 = (kt + 1) * 32;
            #pragma unroll
            for (int i = 0; i < 4; i++)
                pa[i] = *reinterpret_cast<const float4*>(A + a_off[i] + k0 + a_col[i]);
            #pragma unroll
            for (int i = 0; i < 2; i++)
                pb[i] = *reinterpret_cast<const float4*>(W + b_off[i] + k0 + b_col[i]);
        }

        #pragma unroll
        for (int kk = 0; kk < 32; kk += 8) {
            wmma::fragment<wmma::matrix_a, 16, 16, 8, wmma::precision::tf32, wmma::row_major> ah[2], al[2];
            wmma::fragment<wmma::matrix_b, 16, 16, 8, wmma::precision::tf32, wmma::col_major> bh[2], bl[2];
            #pragma unroll
            for (int i = 0; i < 2; i++) {
                wmma::load_matrix_sync(ah[i], As_hi + (wm * 32 + i * 16) * LDA + kk, LDA);
                wmma::load_matrix_sync(al[i], As_lo + (wm * 32 + i * 16) * LDA + kk, LDA);
            }
            #pragma unroll
            for (int j = 0; j < 2; j++) {
                wmma::load_matrix_sync(bh[j], Bs_hi + (wn * 32 + j * 16) * LDA + kk, LDA);
                wmma::load_matrix_sync(bl[j], Bs_lo + (wn * 32 + j * 16) * LDA + kk, LDA);
            }
            #pragma unroll
            for (int i = 0; i < 2; i++)
                #pragma unroll
                for (int j = 0; j < 2; j++) {
                    wmma::mma_sync(cf[i][j], al[i], bh[j], cf[i][j]);
                    wmma::mma_sync(cf[i][j], ah[i], bl[j], cf[i][j]);
                    wmma::mma_sync(cf[i][j], ah[i], bh[j], cf[i][j]);
                }
        }
        __syncthreads();
    }

    #pragma unroll
    for (int i = 0; i < 2; i++)
        #pragma unroll
        for (int j = 0; j < 2; j++)
            wmma::store_matrix_sync(s + (wm * 32 + i * 16) * LDC + wn * 32 + j * 16,
                                    cf[i][j], LDC, wmma::mem_row_major);
    __syncthreads();

    #pragma unroll
    for (int i = 0; i < 8; i++) {
        int idx = tid + i * 256;
        int row = idx >> 4;
        int col = (idx & 15) * 4;
        float4 o;
        o.x = s[row * LDC + col + 0] + biasS[col + 0];
        o.y = s[row * LDC + col + 1] + biasS[col + 1];
        o.z = s[row * LDC + col + 2] + biasS[col + 2];
        o.w = s[row * LDC + col + 3] + biasS[col + 3];
        *reinterpret_cast<float4*>(&g_xw[(size_t)(m0 + row) * Hdim + n0 + col]) = o;
    }
}

// ===========================================================================
// Scan kernels. Shared structure: grid (16 jblk, 8 bblk), 256 threads.
// Warp w consumes k-chunk [w*64,(w+1)*64) produced by jblks {2w, 2w+1}.
// ===========================================================================

// ---- Variant A: cluster(16) + DSMEM mbarrier signaling --------------------
__global__ __launch_bounds__(256) void rnn_scan_cl(const float* __restrict__ Whh)
{
    __shared__ __align__(16) float hs[8 * 512];
    __shared__ __align__(16) float part[8 * 8 * 32];
    __shared__ __align__(8)  unsigned long long mbars[8];   // one per consumer warp

    const int tid  = threadIdx.x;
    const int w    = tid >> 5;
    const int lane = tid & 31;
    const int jblk = blockIdx.x;   // == cluster rank (cluster spans x fully)
    const int bblk = blockIdx.y;
    const int j = jblk * 32 + lane;
    const int rowbase = bblk * 8;

    const uint32_t mb_base = smem_u32(mbars);
    if (tid < 8) MBARRIER_INIT(mb_base + tid * 8, 2);
    __syncthreads();
    asm volatile("barrier.cluster.arrive.aligned;" ::: "memory");
    asm volatile("barrier.cluster.wait.aligned;"   ::: "memory");

    float4 wv[16];
    const float4* Wr = reinterpret_cast<const float4*>(Whh + (size_t)j * Hdim + w * 64);
    #pragma unroll
    for (int i = 0; i < 16; i++) wv[i] = Wr[i];

    float4* hs4 = reinterpret_cast<float4*>(hs);
    const int b2 = tid >> 5, j2 = tid & 31;
    const size_t outbase = (size_t)(rowbase + b2) * Hdim + jblk * 32 + j2;

    int l_b[4], l_q[4];
    #pragma unroll
    for (int i = 0; i < 4; i++) {
        int idx = lane + i * 32;
        l_b[i] = idx >> 4;
        l_q[i] = idx & 15;
    }
    const uint32_t myslot = mb_base + (uint32_t)(jblk >> 1) * 8;

    for (int t = 0; t < Tdim; ++t) {
        const size_t off = (size_t)t * BH + outbase;
        float xv = __ldcg(&g_xw[off]);

        if (t > 0) {
            MBAR_WAIT_CL(mb_base + w * 8, (t - 1) & 1);
            const float4* src = reinterpret_cast<const float4*>(
                g_h + (size_t)(t - 1) * BH + (size_t)rowbase * Hdim);
            #pragma unroll
            for (int i = 0; i < 4; i++)
                hs4[l_b[i] * 128 + w * 16 + l_q[i]] =
                    __ldcg(&src[l_b[i] * 128 + w * 16 + l_q[i]]);
        } else {
            float4 z = make_float4(0.f, 0.f, 0.f, 0.f);
            #pragma unroll
            for (int i = 0; i < 4; i++)
                hs4[l_b[i] * 128 + w * 16 + l_q[i]] = z;
        }
        __syncwarp();

        float acc[8];
        #pragma unroll
        for (int b = 0; b < 8; b++) acc[b] = 0.f;
        #pragma unroll
        for (int i = 0; i < 16; i++) {
            float4 w4 = wv[i];
            #pragma unroll
            for (int b = 0; b < 8; b++) {
                float4 h4 = hs4[b * 128 + w * 16 + i];
                acc[b] = fmaf(h4.w, w4.w,
                          fmaf(h4.z, w4.z,
                           fmaf(h4.y, w4.y,
                            fmaf(h4.x, w4.x, acc[b]))));
            }
        }
        #pragma unroll
        for (int b = 0; b < 8; b++)
            part[(w * 8 + b) * 32 + lane] = acc[b];
        __syncthreads();

        {
            float s2 = 0.f;
            #pragma unroll
            for (int ww = 0; ww < 8; ww++)
                s2 += part[(ww * 8 + b2) * 32 + j2];
            g_h[off] = fmaxf(xv + s2, 0.f);
        }
        __syncthreads();

        // Signal h[t] ready: remote-arrive on slot (jblk>>1) of all 16 CTAs.
        if (t + 1 < Tdim && tid < 16) {
            uint32_t remote;
            asm("mapa.shared::cluster.u32 %0, %1, %2;"
                : "=r"(remote) : "r"(myslot), "r"(tid));
            asm volatile("mbarrier.arrive.release.cluster.shared::cluster.b64 _, [%0];"
                         :: "r"(remote) : "memory");
        }
    }
    asm volatile("barrier.cluster.arrive.aligned;" ::: "memory");
    asm volatile("barrier.cluster.wait.aligned;"   ::: "memory");
}

// ---- Variant B (fallback): padded L2 flags (R8, proven) -------------------
__global__ __launch_bounds__(256) void rnn_scan(const float* __restrict__ Whh, int layer)
{
    __shared__ __align__(16) float hs[8 * 512];
    __shared__ __align__(16) float part[8 * 8 * 32];

    const int tid  = threadIdx.x;
    const int w    = tid >> 5;
    const int lane = tid & 31;
    const int jblk = blockIdx.x;
    const int bblk = blockIdx.y;
    const int j = jblk * 32 + lane;
    const int rowbase = bblk * 8;
    int* myflag = &g_flag[layer][bblk][jblk][0];
    const int* pf = (lane < 2) ? &g_flag[layer][bblk][2 * w + lane][0] : nullptr;

    float4 wv[16];
    const float4* Wr = reinterpret_cast<const float4*>(Whh + (size_t)j * Hdim + w * 64);
    #pragma unroll
    for (int i = 0; i < 16; i++) wv[i] = Wr[i];

    float4* hs4 = reinterpret_cast<float4*>(hs);
    const int b2 = tid >> 5, j2 = tid & 31;
    const size_t outbase = (size_t)(rowbase + b2) * Hdim + jblk * 32 + j2;

    int l_b[4], l_q[4];
    #pragma unroll
    for (int i = 0; i < 4; i++) {
        int idx = lane + i * 32;
        l_b[i] = idx >> 4;
        l_q[i] = idx & 15;
    }

    for (int t = 0; t < Tdim; ++t) {
        const size_t off = (size_t)t * BH + outbase;
        float xv = __ldcg(&g_xw[off]);

        if (t > 0) {
            for (;;) {
                int v = (lane < 2) ? ld_acquire_gpu(pf) : 0x7fffffff;
                if (__all_sync(0xffffffffu, v >= t)) break;
            }
            const float4* src = reinterpret_cast<const float4*>(
                g_h + (size_t)(t - 1) * BH + (size_t)rowbase * Hdim);
            #pragma unroll
            for (int i = 0; i < 4; i++)
                hs4[l_b[i] * 128 + w * 16 + l_q[i]] =
                    __ldcg(&src[l_b[i] * 128 + w * 16 + l_q[i]]);
        } else {
            float4 z = make_float4(0.f, 0.f, 0.f, 0.f);
            #pragma unroll
            for (int i = 0; i < 4; i++)
                hs4[l_b[i] * 128 + w * 16 + l_q[i]] = z;
        }
        __syncwarp();

        float acc[8];
        #pragma unroll
        for (int b = 0; b < 8; b++) acc[b] = 0.f;
        #pragma unroll
        for (int i = 0; i < 16; i++) {
            float4 w4 = wv[i];
            #pragma unroll
            for (int b = 0; b < 8; b++) {
                float4 h4 = hs4[b * 128 + w * 16 + i];
                acc[b] = fmaf(h4.w, w4.w,
                          fmaf(h4.z, w4.z,
                           fmaf(h4.y, w4.y,
                            fmaf(h4.x, w4.x, acc[b]))));
            }
        }
        #pragma unroll
        for (int b = 0; b < 8; b++)
            part[(w * 8 + b) * 32 + lane] = acc[b];
        __syncthreads();

        {
            float s2 = 0.f;
            #pragma unroll
            for (int ww = 0; ww < 8; ww++)
                s2 += part[(ww * 8 + b2) * 32 + j2];
            g_h[off] = fmaxf(xv + s2, 0.f);
        }
        __syncthreads();
        if (tid == 0) st_release_gpu(myflag, t + 1);
    }
}

// ---------------------------------------------------------------------------
// FC + sigmoid: out[b*T + t] = sigmoid(dot(h1[t][b], W_fc) + b_fc)
// ---------------------------------------------------------------------------
__global__ __launch_bounds__(256) void fc_sigmoid(
    const float* __restrict__ wfc, const float* __restrict__ bfc,
    float* __restrict__ out)
{
    int gw   = (blockIdx.x * blockDim.x + threadIdx.x) >> 5;
    int lane = threadIdx.x & 31;
    int t = gw >> 6, b = gw & 63;

    const float4* hp = reinterpret_cast<const float4*>(g_h + (size_t)gw * Hdim);
    const float4* wp = reinterpret_cast<const float4*>(wfc);
    float s = 0.f;
    #pragma unroll
    for (int r = 0; r < 4; r++) {
        float4 hv = hp[lane + r * 32];
        float4 wv = wp[lane + r * 32];
        s += hv.x * wv.x + hv.y * wv.y + hv.z * wv.z + hv.w * wv.w;
    }
    #pragma unroll
    for (int o = 16; o > 0; o >>= 1)
        s += __shfl_xor_sync(0xffffffffu, s, o);
    if (lane == 0) {
        float v = s + bfc[0];
        out[(size_t)b * Tdim + t] = 1.f / (1.f + expf(-v));
    }
}

// ---------------------------------------------------------------------------
extern "C" void kernel_launch(void* const* d_in, const int* in_sizes, int n_in,
                              void* d_out, int out_size)
{
    (void)in_sizes; (void)n_in; (void)out_size;
    const float* x    = (const float*)d_in[0];
    const float* Wih0 = (const float*)d_in[1];
    const float* Whh0 = (const float*)d_in[2];
    const float* bih0 = (const float*)d_in[3];
    const float* bhh0 = (const float*)d_in[4];
    const float* Wih1 = (const float*)d_in[5];
    const float* Whh1 = (const float*)d_in[6];
    const float* bih1 = (const float*)d_in[7];
    const float* bhh1 = (const float*)d_in[8];
    const float* Wfc  = (const float*)d_in[9];
    const float* bfc  = (const float*)d_in[10];
    float* out = (float*)d_out;

    const int dyn_smem = TOT_FL * sizeof(float);  // 61440 B
    static bool attr_set = false;
    if (!attr_set) {
        cudaFuncSetAttribute(proj_tc<Idim, true>,
                             cudaFuncAttributeMaxDynamicSharedMemorySize, dyn_smem);
        cudaFuncSetAttribute(proj_tc<Hdim, false>,
                             cudaFuncAttributeMaxDynamicSharedMemorySize, dyn_smem);
        cudaFuncSetAttribute(rnn_scan_cl,
                             cudaFuncAttributeNonPortableClusterSizeAllowed, 1);
        attr_set = true;
    }

    // Probe cluster(16) support without launching (capture-safe query)
    cudaLaunchConfig_t cfg = {};
    cfg.gridDim  = dim3(16, 8, 1);
    cfg.blockDim = dim3(256, 1, 1);
    cfg.dynamicSmemBytes = 0;
    cfg.stream = 0;
    cudaLaunchAttribute cat[1];
    cat[0].id = cudaLaunchAttributeClusterDimension;
    cat[0].val.clusterDim.x = 16;
    cat[0].val.clusterDim.y = 1;
    cat[0].val.clusterDim.z = 1;
    cfg.attrs = cat;
    cfg.numAttrs = 1;
    int nclust = 0;
    cudaError_t q = cudaOccupancyMaxActiveClusters(&nclust, rnn_scan_cl, &cfg);
    bool use_cl = (q == cudaSuccess && nclust > 0);
    if (!use_cl) (void)cudaGetLastError();   // clear sticky error

    dim3 gemm_grid(8, 256);
    dim3 scan_grid(16, 8);

    zero_flags_k<<<32, 512>>>();

    // Layer 0
    proj_tc<Idim, true><<<gemm_grid, 256, dyn_smem>>>(x, Wih0, bih0, bhh0);
    if (use_cl) cudaLaunchKernelEx(&cfg, rnn_scan_cl, Whh0);
    else        rnn_scan<<<scan_grid, 256>>>(Whh0, 0);

    // Layer 1
    proj_tc<Hdim, false><<<gemm_grid, 256, dyn_smem>>>(x, Wih1, bih1, bhh1);
    if (use_cl) cudaLaunchKernelEx(&cfg, rnn_scan_cl, Whh1);
    else        rnn_scan<<<scan_grid, 256>>>(Whh1, 1);

    // Head
    fc_sigmoid<<<4096, 256>>>(Wfc, bfc, out);
}

// round 10
// speedup vs baseline: 1.1246x; 1.1246x over previous
#include <cuda_runtime.h>
#include <math.h>
#include <stdint.h>
#include <mma.h>

using namespace nvcuda;

#define Bdim 64
#define Tdim 512
#define Idim 256
#define Hdim 512
#define BH   (Bdim*Hdim)   // 32768

// Scratch (device globals: no allocations allowed)
__device__ float g_xw[(size_t)Tdim*Bdim*Hdim];  // 64 MB, [T,B,H] rows m=t*64+b
__device__ float g_h [(size_t)Tdim*Bdim*Hdim];  // 64 MB, [T,B,H]
// Row flags: [layer][bblk][jblk][row*4] -- each producer CTA owns a 128B line;
// its 8 reduce warps write rows at 16B stride within that line.
__device__ int   g_flag[2][8][16][32];

__global__ void zero_flags_k() {
    int i = blockIdx.x * blockDim.x + threadIdx.x;
    if (i < 2 * 8 * 16 * 32) ((int*)g_flag)[i] = 0;
}

__device__ __forceinline__ void st_release_gpu(int* p, int v) {
    asm volatile("st.release.gpu.u32 [%0], %1;" :: "l"(p), "r"(v) : "memory");
}
__device__ __forceinline__ int ld_acquire_gpu(const int* p) {
    int v;
    asm volatile("ld.acquire.gpu.u32 %0, [%1];" : "=r"(v) : "l"(p) : "memory");
    return v;
}

// ---------------------------------------------------------------------------
// 3xTF32 tensor-core projection GEMM (near-fp32 accuracy).
// g_xw[m][n] = sum_k A[m][k] * W[n][k] + b1[n] + b2[n]
// v = hi + lo (hi = tf32-rounded); C += hi*hi + hi*lo + lo*hi.
// CTA tile: M=128, N=64, K chunked by 32. 8 warps, each 32x32 (2x2 wmma 16x16x8).
// FIRST: A = x with layout [B,T,I]  (row m=t*64+b -> offset (b*T+t)*KD)
// else : A = g_h with row-major rows m (offset m*KD)
// ---------------------------------------------------------------------------
#define LDA 40                       // 32 + 8 skew
#define A_FL (128 * LDA)
#define B_FL (64 * LDA)
#define TOT_FL (2 * (A_FL + B_FL))   // 15360 floats = 61440 B
#define LDC 72                       // 64 + 8 skew

template<int KD, bool FIRST>
__global__ __launch_bounds__(256, 2) void proj_tc(
    const float* __restrict__ xin, const float* __restrict__ W,
    const float* __restrict__ b1,  const float* __restrict__ b2)
{
    extern __shared__ float s[];     // [A_hi | A_lo | B_hi | B_lo]; reused as C
    float* As_hi = s;
    float* As_lo = s + A_FL;
    float* Bs_hi = s + 2 * A_FL;
    float* Bs_lo = s + 2 * A_FL + B_FL;
    __shared__ float biasS[64];

    const float* __restrict__ A = FIRST ? xin : g_h;
    const int tid = threadIdx.x;
    const int wid = tid >> 5;
    const int n0 = blockIdx.x * 64;
    const int m0 = blockIdx.y * 128;
    const int wm = wid & 3;
    const int wn = wid >> 2;

    if (tid < 64) biasS[tid] = b1[n0 + tid] + b2[n0 + tid];

    int a_row[4], a_col[4];
    #pragma unroll
    for (int i = 0; i < 4; i++) {
        int idx = tid + i * 256;
        a_row[i] = idx >> 3;
        a_col[i] = (idx & 7) * 4;
    }
    int b_row[2], b_col[2];
    #pragma unroll
    for (int i = 0; i < 2; i++) {
        int idx = tid + i * 256;
        b_row[i] = idx >> 3;
        b_col[i] = (idx & 7) * 4;
    }

    size_t a_off[4];
    #pragma unroll
    for (int i = 0; i < 4; i++) {
        int m = m0 + a_row[i];
        a_off[i] = FIRST ? ((size_t)(m & 63) * Tdim + (m >> 6)) * KD
                         : (size_t)m * KD;
    }
    size_t b_off[2];
    #pragma unroll
    for (int i = 0; i < 2; i++)
        b_off[i] = (size_t)(n0 + b_row[i]) * KD;

    wmma::fragment<wmma::accumulator, 16, 16, 8, float> cf[2][2];
    #pragma unroll
    for (int i = 0; i < 2; i++)
        #pragma unroll
        for (int j = 0; j < 2; j++)
            wmma::fill_fragment(cf[i][j], 0.0f);

    float4 pa[4], pb[2];
    #pragma unroll
    for (int i = 0; i < 4; i++)
        pa[i] = *reinterpret_cast<const float4*>(A + a_off[i] + a_col[i]);
    #pragma unroll
    for (int i = 0; i < 2; i++)
        pb[i] = *reinterpret_cast<const float4*>(W + b_off[i] + b_col[i]);

    const int KT = KD / 32;
    for (int kt = 0; kt < KT; ++kt) {
        #pragma unroll
        for (int i = 0; i < 4; i++) {
            int o = a_row[i] * LDA + a_col[i];
            float hx = wmma::__float_to_tf32(pa[i].x);
            float hy = wmma::__float_to_tf32(pa[i].y);
            float hz = wmma::__float_to_tf32(pa[i].z);
            float hw = wmma::__float_to_tf32(pa[i].w);
            As_hi[o+0] = hx; As_hi[o+1] = hy; As_hi[o+2] = hz; As_hi[o+3] = hw;
            As_lo[o+0] = pa[i].x - hx; As_lo[o+1] = pa[i].y - hy;
            As_lo[o+2] = pa[i].z - hz; As_lo[o+3] = pa[i].w - hw;
        }
        #pragma unroll
        for (int i = 0; i < 2; i++) {
            int o = b_row[i] * LDA + b_col[i];
            float hx = wmma::__float_to_tf32(pb[i].x);
            float hy = wmma::__float_to_tf32(pb[i].y);
            float hz = wmma::__float_to_tf32(pb[i].z);
            float hw = wmma::__float_to_tf32(pb[i].w);
            Bs_hi[o+0] = hx; Bs_hi[o+1] = hy; Bs_hi[o+2] = hz; Bs_hi[o+3] = hw;
            Bs_lo[o+0] = pb[i].x - hx; Bs_lo[o+1] = pb[i].y - hy;
            Bs_lo[o+2] = pb[i].z - hz; Bs_lo[o+3] = pb[i].w - hw;
        }
        __syncthreads();

        if (kt + 1 < KT) {
            int k0 = (kt + 1) * 32;
            #pragma unroll
            for (int i = 0; i < 4; i++)
                pa[i] = *reinterpret_cast<const float4*>(A + a_off[i] + k0 + a_col[i]);
            #pragma unroll
            for (int i = 0; i < 2; i++)
                pb[i] = *reinterpret_cast<const float4*>(W + b_off[i] + k0 + b_col[i]);
        }

        #pragma unroll
        for (int kk = 0; kk < 32; kk += 8) {
            wmma::fragment<wmma::matrix_a, 16, 16, 8, wmma::precision::tf32, wmma::row_major> ah[2], al[2];
            wmma::fragment<wmma::matrix_b, 16, 16, 8, wmma::precision::tf32, wmma::col_major> bh[2], bl[2];
            #pragma unroll
            for (int i = 0; i < 2; i++) {
                wmma::load_matrix_sync(ah[i], As_hi + (wm * 32 + i * 16) * LDA + kk, LDA);
                wmma::load_matrix_sync(al[i], As_lo + (wm * 32 + i * 16) * LDA + kk, LDA);
            }
            #pragma unroll
            for (int j = 0; j < 2; j++) {
                wmma::load_matrix_sync(bh[j], Bs_hi + (wn * 32 + j * 16) * LDA + kk, LDA);
                wmma::load_matrix_sync(bl[j], Bs_lo + (wn * 32 + j * 16) * LDA + kk, LDA);
            }
            #pragma unroll
            for (int i = 0; i < 2; i++)
                #pragma unroll
                for (int j = 0; j < 2; j++) {
                    wmma::mma_sync(cf[i][j], al[i], bh[j], cf[i][j]);
                    wmma::mma_sync(cf[i][j], ah[i], bl[j], cf[i][j]);
                    wmma::mma_sync(cf[i][j], ah[i], bh[j], cf[i][j]);
                }
        }
        __syncthreads();
    }

    #pragma unroll
    for (int i = 0; i < 2; i++)
        #pragma unroll
        for (int j = 0; j < 2; j++)
            wmma::store_matrix_sync(s + (wm * 32 + i * 16) * LDC + wn * 32 + j * 16,
                                    cf[i][j], LDC, wmma::mem_row_major);
    __syncthreads();

    #pragma unroll
    for (int i = 0; i < 8; i++) {
        int idx = tid + i * 256;
        int row = idx >> 4;
        int col = (idx & 15) * 4;
        float4 o;
        o.x = s[row * LDC + col + 0] + biasS[col + 0];
        o.y = s[row * LDC + col + 1] + biasS[col + 1];
        o.z = s[row * LDC + col + 2] + biasS[col + 2];
        o.w = s[row * LDC + col + 3] + biasS[col + 3];
        *reinterpret_cast<float4*>(&g_xw[(size_t)(m0 + row) * Hdim + n0 + col]) = o;
    }
}

// ---------------------------------------------------------------------------
// Recurrent scan: h[t] = relu(xw[t] + h[t-1] @ Whh^T), persistent kernel.
// Grid (16 j-blocks, 8 b-blocks) = 128 CTAs, 256 threads each.
// Per-warp pipeline (R8) + per-row flags + part double-buffer:
//   warp w polls the 16 row-flags of its 2 producers (jblk 2w, 2w+1), loads
//   its own 2KB h slice, computes partials (syncwarp only); one CTA barrier
//   publishes partials; reduce-warp b stores g_h row b and releases row-flag b
//   immediately (syncwarp + lane0 st.release) -- no trailing CTA barrier.
// part[] is parity double-buffered; distance-2 reuse is ordered transitively
// through the producer/consumer flag chain.
// ---------------------------------------------------------------------------
__global__ __launch_bounds__(256) void rnn_scan(const float* __restrict__ Whh, int layer)
{
    __shared__ __align__(16) float hs[8 * 512];          // h_prev slice (8 batch rows)
    __shared__ __align__(16) float part[2][8 * 8 * 32];  // parity double-buffered

    const int tid  = threadIdx.x;
    const int w    = tid >> 5;
    const int lane = tid & 31;
    const int jblk = blockIdx.x;   // 0..15
    const int bblk = blockIdx.y;   // 0..7
    const int j = jblk * 32 + lane;
    const int rowbase = bblk * 8;
    // Consumer poll targets: lane<16 -> producer (2w + lane/8), row (lane&7)
    const int* pf = (lane < 16)
        ? &g_flag[layer][bblk][2 * w + (lane >> 3)][(lane & 7) * 4] : nullptr;
    int* relflag = &g_flag[layer][bblk][jblk][w * 4];   // this warp's row flag

    // Weight-stationary registers: Whh[j][w*64 .. w*64+63]
    float4 wv[16];
    const float4* Wr = reinterpret_cast<const float4*>(Whh + (size_t)j * Hdim + w * 64);
    #pragma unroll
    for (int i = 0; i < 16; i++) wv[i] = Wr[i];

    float4* hs4 = reinterpret_cast<float4*>(hs);
    const int b2 = tid >> 5, j2 = tid & 31;
    const size_t outbase = (size_t)(rowbase + b2) * Hdim + jblk * 32 + j2;

    int l_b[4], l_q[4];
    #pragma unroll
    for (int i = 0; i < 4; i++) {
        int idx = lane + i * 32;      // 0..127
        l_b[i] = idx >> 4;            // row 0..7
        l_q[i] = idx & 15;            // float4 col within warp chunk
    }

    for (int t = 0; t < Tdim; ++t) {
        // Prefetch xw for this thread's output slot (independent of h[t-1])
        const size_t off = (size_t)t * BH + outbase;
        float xv = __ldcg(&g_xw[off]);
        float* pbuf = part[t & 1];

        if (t > 0) {
            for (;;) {
                int v = (lane < 16) ? ld_acquire_gpu(pf) : 0x7fffffff;
                if (__all_sync(0xffffffffu, v >= t)) break;
            }
            const float4* src = reinterpret_cast<const float4*>(
                g_h + (size_t)(t - 1) * BH + (size_t)rowbase * Hdim);
            #pragma unroll
            for (int i = 0; i < 4; i++)
                hs4[l_b[i] * 128 + w * 16 + l_q[i]] =
                    __ldcg(&src[l_b[i] * 128 + w * 16 + l_q[i]]);
        } else {
            float4 z = make_float4(0.f, 0.f, 0.f, 0.f);
            #pragma unroll
            for (int i = 0; i < 4; i++)
                hs4[l_b[i] * 128 + w * 16 + l_q[i]] = z;
        }
        __syncwarp();   // warp w reads only its own hs slice

        float acc[8];
        #pragma unroll
        for (int b = 0; b < 8; b++) acc[b] = 0.f;
        #pragma unroll
        for (int i = 0; i < 16; i++) {
            float4 w4 = wv[i];
            #pragma unroll
            for (int b = 0; b < 8; b++) {
                float4 h4 = hs4[b * 128 + w * 16 + i];   // warp-uniform -> broadcast
                acc[b] = fmaf(h4.w, w4.w,
                          fmaf(h4.z, w4.z,
                           fmaf(h4.y, w4.y,
                            fmaf(h4.x, w4.x, acc[b]))));
            }
        }
        #pragma unroll
        for (int b = 0; b < 8; b++)
            pbuf[(w * 8 + b) * 32 + lane] = acc[b];
        __syncthreads();   // publish partials (the ONLY CTA barrier per step)

        {
            float s2 = 0.f;
            #pragma unroll
            for (int ww = 0; ww < 8; ww++)
                s2 += pbuf[(ww * 8 + b2) * 32 + j2];
            g_h[off] = fmaxf(xv + s2, 0.f);
        }
        __syncwarp();                       // all 32 row stores of this warp done
        if (lane == 0) st_release_gpu(relflag, t + 1);
    }
}

// ---------------------------------------------------------------------------
// FC + sigmoid: out[b*T + t] = sigmoid(dot(h1[t][b], W_fc) + b_fc)
// ---------------------------------------------------------------------------
__global__ __launch_bounds__(256) void fc_sigmoid(
    const float* __restrict__ wfc, const float* __restrict__ bfc,
    float* __restrict__ out)
{
    int gw   = (blockIdx.x * blockDim.x + threadIdx.x) >> 5;  // 0..32767
    int lane = threadIdx.x & 31;
    int t = gw >> 6, b = gw & 63;

    const float4* hp = reinterpret_cast<const float4*>(g_h + (size_t)gw * Hdim);
    const float4* wp = reinterpret_cast<const float4*>(wfc);
    float s = 0.f;
    #pragma unroll
    for (int r = 0; r < 4; r++) {
        float4 hv = hp[lane + r * 32];
        float4 wv = wp[lane + r * 32];
        s += hv.x * wv.x + hv.y * wv.y + hv.z * wv.z + hv.w * wv.w;
    }
    #pragma unroll
    for (int o = 16; o > 0; o >>= 1)
        s += __shfl_xor_sync(0xffffffffu, s, o);
    if (lane == 0) {
        float v = s + bfc[0];
        out[(size_t)b * Tdim + t] = 1.f / (1.f + expf(-v));
    }
}

// ---------------------------------------------------------------------------
extern "C" void kernel_launch(void* const* d_in, const int* in_sizes, int n_in,
                              void* d_out, int out_size)
{
    (void)in_sizes; (void)n_in; (void)out_size;
    const float* x    = (const float*)d_in[0];
    const float* Wih0 = (const float*)d_in[1];
    const float* Whh0 = (const float*)d_in[2];
    const float* bih0 = (const float*)d_in[3];
    const float* bhh0 = (const float*)d_in[4];
    const float* Wih1 = (const float*)d_in[5];
    const float* Whh1 = (const float*)d_in[6];
    const float* bih1 = (const float*)d_in[7];
    const float* bhh1 = (const float*)d_in[8];
    const float* Wfc  = (const float*)d_in[9];
    const float* bfc  = (const float*)d_in[10];
    float* out = (float*)d_out;

    const int dyn_smem = TOT_FL * sizeof(float);  // 61440 B
    static bool attr_set = false;
    if (!attr_set) {
        cudaFuncSetAttribute(proj_tc<Idim, true>,
                             cudaFuncAttributeMaxDynamicSharedMemorySize, dyn_smem);
        cudaFuncSetAttribute(proj_tc<Hdim, false>,
                             cudaFuncAttributeMaxDynamicSharedMemorySize, dyn_smem);
        attr_set = true;
    }

    dim3 gemm_grid(8, 256);   // N/64, M/128
    dim3 scan_grid(16, 8);    // j-blocks, b-blocks

    zero_flags_k<<<16, 512>>>();

    // Layer 0
    proj_tc<Idim, true><<<gemm_grid, 256, dyn_smem>>>(x, Wih0, bih0, bhh0);
    rnn_scan<<<scan_grid, 256>>>(Whh0, 0);

    // Layer 1
    proj_tc<Hdim, false><<<gemm_grid, 256, dyn_smem>>>(x, Wih1, bih1, bhh1);
    rnn_scan<<<scan_grid, 256>>>(Whh1, 1);

    // Head
    fc_sigmoid<<<4096, 256>>>(Wfc, bfc, out);
}

// round 11
// speedup vs baseline: 1.1607x; 1.0320x over previous
#include <cuda_runtime.h>
#include <math.h>
#include <stdint.h>
#include <mma.h>

using namespace nvcuda;

#define Bdim 64
#define Tdim 512
#define Idim 256
#define Hdim 512
#define BH   (Bdim*Hdim)   // 32768

// Scratch (device globals: no allocations allowed)
__device__ float g_xw[(size_t)Tdim*Bdim*Hdim];  // 64 MB, [T,B,H] rows m=t*64+b
__device__ float g_h [(size_t)Tdim*Bdim*Hdim];  // 64 MB, [T,B,H]
__device__ int   g_flag[2][8][32][32];          // flags padded: one 128B line each

__global__ void zero_flags_k() {
    int i = blockIdx.x * blockDim.x + threadIdx.x;
    if (i < 2 * 8 * 32 * 32) ((int*)g_flag)[i] = 0;
}

__device__ __forceinline__ void st_release_gpu(int* p, int v) {
    asm volatile("st.release.gpu.u32 [%0], %1;" :: "l"(p), "r"(v) : "memory");
}
__device__ __forceinline__ int ld_acquire_gpu(const int* p) {
    int v;
    asm volatile("ld.acquire.gpu.u32 %0, [%1];" : "=r"(v) : "l"(p) : "memory");
    return v;
}

// ---------------------------------------------------------------------------
// 3xTF32 tensor-core projection GEMM (near-fp32 accuracy), double-buffered.
// g_xw[m][n] = sum_k A[m][k] * W[n][k] + b1[n] + b2[n]
// v = hi + lo (hi = tf32-rounded); C += hi*hi + hi*lo + lo*hi.
// CTA tile: M=128, N=64, K chunked by 32. 8 warps, each 32x32 (2x2 wmma 16x16x8).
// Staging of chunk k+1 (cvt + STS into the opposite buffer) overlaps the MMA
// consumption of chunk k; ONE __syncthreads per chunk.
// FIRST: A = x with layout [B,T,I]  (row m=t*64+b -> offset (b*T+t)*KD)
// else : A = g_h with row-major rows m (offset m*KD)
// ---------------------------------------------------------------------------
#define LDA 36                       // 32 + 4 skew (16B-aligned rows)
#define A_FL (128 * LDA)             // 4608
#define B_FL (64 * LDA)              // 2304
#define BUF_FL (2 * (A_FL + B_FL))   // 13824 floats per buffer (hi+lo, A+B)
#define TOT_FL (2 * BUF_FL)          // 27648 floats = 110592 B
#define LDC 72                       // 64 + 8 skew (epilogue C)

template<int KD, bool FIRST>
__global__ __launch_bounds__(256, 2) void proj_tc(
    const float* __restrict__ xin, const float* __restrict__ W,
    const float* __restrict__ b1,  const float* __restrict__ b2)
{
    extern __shared__ float s[];     // two staging buffers; reused as C
    __shared__ float biasS[64];

    const float* __restrict__ A = FIRST ? xin : g_h;
    const int tid = threadIdx.x;
    const int wid = tid >> 5;
    const int n0 = blockIdx.x * 64;
    const int m0 = blockIdx.y * 128;
    const int wm = wid & 3;
    const int wn = wid >> 2;

    if (tid < 64) biasS[tid] = b1[n0 + tid] + b2[n0 + tid];

    int a_row[4], a_col[4];
    #pragma unroll
    for (int i = 0; i < 4; i++) {
        int idx = tid + i * 256;
        a_row[i] = idx >> 3;
        a_col[i] = (idx & 7) * 4;
    }
    int b_row[2], b_col[2];
    #pragma unroll
    for (int i = 0; i < 2; i++) {
        int idx = tid + i * 256;
        b_row[i] = idx >> 3;
        b_col[i] = (idx & 7) * 4;
    }

    size_t a_off[4];
    #pragma unroll
    for (int i = 0; i < 4; i++) {
        int m = m0 + a_row[i];
        a_off[i] = FIRST ? ((size_t)(m & 63) * Tdim + (m >> 6)) * KD
                         : (size_t)m * KD;
    }
    size_t b_off[2];
    #pragma unroll
    for (int i = 0; i < 2; i++)
        b_off[i] = (size_t)(n0 + b_row[i]) * KD;

    wmma::fragment<wmma::accumulator, 16, 16, 8, float> cf[2][2];
    #pragma unroll
    for (int i = 0; i < 2; i++)
        #pragma unroll
        for (int j = 0; j < 2; j++)
            wmma::fill_fragment(cf[i][j], 0.0f);

    float4 pa[4], pb[2];

    // Stage regs (one 32-wide chunk) into buffer `base` as hi/lo split.
    auto stage = [&](float* base) {
        float* Ah = base;
        float* Al = base + A_FL;
        float* Bh = base + 2 * A_FL;
        float* Bl = base + 2 * A_FL + B_FL;
        #pragma unroll
        for (int i = 0; i < 4; i++) {
            int o = a_row[i] * LDA + a_col[i];
            float hx = wmma::__float_to_tf32(pa[i].x);
            float hy = wmma::__float_to_tf32(pa[i].y);
            float hz = wmma::__float_to_tf32(pa[i].z);
            float hw = wmma::__float_to_tf32(pa[i].w);
            Ah[o+0] = hx; Ah[o+1] = hy; Ah[o+2] = hz; Ah[o+3] = hw;
            Al[o+0] = pa[i].x - hx; Al[o+1] = pa[i].y - hy;
            Al[o+2] = pa[i].z - hz; Al[o+3] = pa[i].w - hw;
        }
        #pragma unroll
        for (int i = 0; i < 2; i++) {
            int o = b_row[i] * LDA + b_col[i];
            float hx = wmma::__float_to_tf32(pb[i].x);
            float hy = wmma::__float_to_tf32(pb[i].y);
            float hz = wmma::__float_to_tf32(pb[i].z);
            float hw = wmma::__float_to_tf32(pb[i].w);
            Bh[o+0] = hx; Bh[o+1] = hy; Bh[o+2] = hz; Bh[o+3] = hw;
            Bl[o+0] = pb[i].x - hx; Bl[o+1] = pb[i].y - hy;
            Bl[o+2] = pb[i].z - hz; Bl[o+3] = pb[i].w - hw;
        }
    };
    auto gload = [&](int kt) {
        int k0 = kt * 32;
        #pragma unroll
        for (int i = 0; i < 4; i++)
            pa[i] = *reinterpret_cast<const float4*>(A + a_off[i] + k0 + a_col[i]);
        #pragma unroll
        for (int i = 0; i < 2; i++)
            pb[i] = *reinterpret_cast<const float4*>(W + b_off[i] + k0 + b_col[i]);
    };

    const int KT = KD / 32;
    gload(0);
    stage(s);                 // buffer 0 <- chunk 0
    if (KT > 1) gload(1);
    __syncthreads();

    for (int kt = 0; kt < KT; ++kt) {
        float* cur = s + (kt & 1) * BUF_FL;
        // Stage chunk kt+1 into the other buffer (independent of MMAs on cur)
        if (kt + 1 < KT) stage(s + ((kt + 1) & 1) * BUF_FL);

        const float* Ah = cur;
        const float* Al = cur + A_FL;
        const float* Bh = cur + 2 * A_FL;
        const float* Bl = cur + 2 * A_FL + B_FL;
        #pragma unroll
        for (int kk = 0; kk < 32; kk += 8) {
            wmma::fragment<wmma::matrix_a, 16, 16, 8, wmma::precision::tf32, wmma::row_major> ah[2], al[2];
            wmma::fragment<wmma::matrix_b, 16, 16, 8, wmma::precision::tf32, wmma::col_major> bh[2], bl[2];
            #pragma unroll
            for (int i = 0; i < 2; i++) {
                wmma::load_matrix_sync(ah[i], Ah + (wm * 32 + i * 16) * LDA + kk, LDA);
                wmma::load_matrix_sync(al[i], Al + (wm * 32 + i * 16) * LDA + kk, LDA);
            }
            #pragma unroll
            for (int j = 0; j < 2; j++) {
                wmma::load_matrix_sync(bh[j], Bh + (wn * 32 + j * 16) * LDA + kk, LDA);
                wmma::load_matrix_sync(bl[j], Bl + (wn * 32 + j * 16) * LDA + kk, LDA);
            }
            #pragma unroll
            for (int i = 0; i < 2; i++)
                #pragma unroll
                for (int j = 0; j < 2; j++) {
                    wmma::mma_sync(cf[i][j], al[i], bh[j], cf[i][j]);
                    wmma::mma_sync(cf[i][j], ah[i], bl[j], cf[i][j]);
                    wmma::mma_sync(cf[i][j], ah[i], bh[j], cf[i][j]);
                }
        }
        // Prefetch chunk kt+2 into regs (staging consumed the old values)
        if (kt + 2 < KT) gload(kt + 2);
        __syncthreads();
    }

    // Epilogue: accum -> smem -> (+bias) -> g_xw
    #pragma unroll
    for (int i = 0; i < 2; i++)
        #pragma unroll
        for (int j = 0; j < 2; j++)
            wmma::store_matrix_sync(s + (wm * 32 + i * 16) * LDC + wn * 32 + j * 16,
                                    cf[i][j], LDC, wmma::mem_row_major);
    __syncthreads();

    #pragma unroll
    for (int i = 0; i < 8; i++) {
        int idx = tid + i * 256;
        int row = idx >> 4;
        int col = (idx & 15) * 4;
        float4 o;
        o.x = s[row * LDC + col + 0] + biasS[col + 0];
        o.y = s[row * LDC + col + 1] + biasS[col + 1];
        o.z = s[row * LDC + col + 2] + biasS[col + 2];
        o.w = s[row * LDC + col + 3] + biasS[col + 3];
        *reinterpret_cast<float4*>(&g_xw[(size_t)(m0 + row) * Hdim + n0 + col]) = o;
    }
}

// ---------------------------------------------------------------------------
// Recurrent scan (R8, proven best): h[t] = relu(xw[t] + h[t-1] @ Whh^T).
// Grid (16 j-blocks, 8 b-blocks) = 128 CTAs, 256 threads each.
// Warp w consumes k-chunk [w*64,(w+1)*64) produced by jblks {2w, 2w+1}: polls
// its own two flags (each on a private 128B line), loads its own 2KB h slice,
// computes partials with only a __syncwarp; CTA barrier only at the reduce.
// ---------------------------------------------------------------------------
__global__ __launch_bounds__(256) void rnn_scan(const float* __restrict__ Whh, int layer)
{
    __shared__ __align__(16) float hs[8 * 512];
    __shared__ __align__(16) float part[8 * 8 * 32];

    const int tid  = threadIdx.x;
    const int w    = tid >> 5;
    const int lane = tid & 31;
    const int jblk = blockIdx.x;
    const int bblk = blockIdx.y;
    const int j = jblk * 32 + lane;
    const int rowbase = bblk * 8;
    int* myflag = &g_flag[layer][bblk][jblk][0];
    const int* pf = (lane < 2) ? &g_flag[layer][bblk][2 * w + lane][0] : nullptr;

    float4 wv[16];
    const float4* Wr = reinterpret_cast<const float4*>(Whh + (size_t)j * Hdim + w * 64);
    #pragma unroll
    for (int i = 0; i < 16; i++) wv[i] = Wr[i];

    float4* hs4 = reinterpret_cast<float4*>(hs);
    const int b2 = tid >> 5, j2 = tid & 31;
    const size_t outbase = (size_t)(rowbase + b2) * Hdim + jblk * 32 + j2;

    int l_b[4], l_q[4];
    #pragma unroll
    for (int i = 0; i < 4; i++) {
        int idx = lane + i * 32;
        l_b[i] = idx >> 4;
        l_q[i] = idx & 15;
    }

    for (int t = 0; t < Tdim; ++t) {
        const size_t off = (size_t)t * BH + outbase;
        float xv = __ldcg(&g_xw[off]);

        if (t > 0) {
            for (;;) {
                int v = (lane < 2) ? ld_acquire_gpu(pf) : 0x7fffffff;
                if (__all_sync(0xffffffffu, v >= t)) break;
            }
            const float4* src = reinterpret_cast<const float4*>(
                g_h + (size_t)(t - 1) * BH + (size_t)rowbase * Hdim);
            #pragma unroll
            for (int i = 0; i < 4; i++)
                hs4[l_b[i] * 128 + w * 16 + l_q[i]] =
                    __ldcg(&src[l_b[i] * 128 + w * 16 + l_q[i]]);
        } else {
            float4 z = make_float4(0.f, 0.f, 0.f, 0.f);
            #pragma unroll
            for (int i = 0; i < 4; i++)
                hs4[l_b[i] * 128 + w * 16 + l_q[i]] = z;
        }
        __syncwarp();

        float acc[8];
        #pragma unroll
        for (int b = 0; b < 8; b++) acc[b] = 0.f;
        #pragma unroll
        for (int i = 0; i < 16; i++) {
            float4 w4 = wv[i];
            #pragma unroll
            for (int b = 0; b < 8; b++) {
                float4 h4 = hs4[b * 128 + w * 16 + i];
                acc[b] = fmaf(h4.w, w4.w,
                          fmaf(h4.z, w4.z,
                           fmaf(h4.y, w4.y,
                            fmaf(h4.x, w4.x, acc[b]))));
            }
        }
        #pragma unroll
        for (int b = 0; b < 8; b++)
            part[(w * 8 + b) * 32 + lane] = acc[b];
        __syncthreads();

        {
            float s2 = 0.f;
            #pragma unroll
            for (int ww = 0; ww < 8; ww++)
                s2 += part[(ww * 8 + b2) * 32 + j2];
            g_h[off] = fmaxf(xv + s2, 0.f);
        }
        __syncthreads();
        if (tid == 0) st_release_gpu(myflag, t + 1);
    }
}

// ---------------------------------------------------------------------------
// FC + sigmoid: out[b*T + t] = sigmoid(dot(h1[t][b], W_fc) + b_fc)
// ---------------------------------------------------------------------------
__global__ __launch_bounds__(256) void fc_sigmoid(
    const float* __restrict__ wfc, const float* __restrict__ bfc,
    float* __restrict__ out)
{
    int gw   = (blockIdx.x * blockDim.x + threadIdx.x) >> 5;
    int lane = threadIdx.x & 31;
    int t = gw >> 6, b = gw & 63;

    const float4* hp = reinterpret_cast<const float4*>(g_h + (size_t)gw * Hdim);
    const float4* wp = reinterpret_cast<const float4*>(wfc);
    float s = 0.f;
    #pragma unroll
    for (int r = 0; r < 4; r++) {
        float4 hv = hp[lane + r * 32];
        float4 wv = wp[lane + r * 32];
        s += hv.x * wv.x + hv.y * wv.y + hv.z * wv.z + hv.w * wv.w;
    }
    #pragma unroll
    for (int o = 16; o > 0; o >>= 1)
        s += __shfl_xor_sync(0xffffffffu, s, o);
    if (lane == 0) {
        float v = s + bfc[0];
        out[(size_t)b * Tdim + t] = 1.f / (1.f + expf(-v));
    }
}

// ---------------------------------------------------------------------------
extern "C" void kernel_launch(void* const* d_in, const int* in_sizes, int n_in,
                              void* d_out, int out_size)
{
    (void)in_sizes; (void)n_in; (void)out_size;
    const float* x    = (const float*)d_in[0];
    const float* Wih0 = (const float*)d_in[1];
    const float* Whh0 = (const float*)d_in[2];
    const float* bih0 = (const float*)d_in[3];
    const float* bhh0 = (const float*)d_in[4];
    const float* Wih1 = (const float*)d_in[5];
    const float* Whh1 = (const float*)d_in[6];
    const float* bih1 = (const float*)d_in[7];
    const float* bhh1 = (const float*)d_in[8];
    const float* Wfc  = (const float*)d_in[9];
    const float* bfc  = (const float*)d_in[10];
    float* out = (float*)d_out;

    const int dyn_smem = TOT_FL * sizeof(float);  // 110592 B
    static bool attr_set = false;
    if (!attr_set) {
        cudaFuncSetAttribute(proj_tc<Idim, true>,
                             cudaFuncAttributeMaxDynamicSharedMemorySize, dyn_smem);
        cudaFuncSetAttribute(proj_tc<Hdim, false>,
                             cudaFuncAttributeMaxDynamicSharedMemorySize, dyn_smem);
        attr_set = true;
    }

    dim3 gemm_grid(8, 256);   // N/64, M/128
    dim3 scan_grid(16, 8);    // j-blocks, b-blocks

    zero_flags_k<<<32, 512>>>();

    // Layer 0
    proj_tc<Idim, true><<<gemm_grid, 256, dyn_smem>>>(x, Wih0, bih0, bhh0);
    rnn_scan<<<scan_grid, 256>>>(Whh0, 0);

    // Layer 1
    proj_tc<Hdim, false><<<gemm_grid, 256, dyn_smem>>>(x, Wih1, bih1, bhh1);
    rnn_scan<<<scan_grid, 256>>>(Whh1, 1);

    // Head
    fc_sigmoid<<<4096, 256>>>(Wfc, bfc, out);
}

// round 12
// speedup vs baseline: 1.2256x; 1.0559x over previous
#include <cuda_runtime.h>
#include <math.h>
#include <stdint.h>
#include <mma.h>

using namespace nvcuda;

#define Bdim 64
#define Tdim 512
#define Idim 256
#define Hdim 512
#define BH   (Bdim*Hdim)   // 32768

// Scratch (device globals: no allocations allowed)
__device__ float g_xw0[(size_t)Tdim*Bdim*Hdim];  // layer-0 input projection
__device__ float g_xw1[(size_t)Tdim*Bdim*Hdim];  // layer-1 input projection
__device__ float g_h  [(size_t)Tdim*Bdim*Hdim];  // hidden states (layer0 then layer1)
__device__ int   g_flag[2][8][32][32];           // flags padded: one 128B line each

__global__ void zero_flags_k() {
    int i = blockIdx.x * blockDim.x + threadIdx.x;
    if (i < 2 * 8 * 32 * 32) ((int*)g_flag)[i] = 0;
}

__device__ __forceinline__ void st_release_gpu(int* p, int v) {
    asm volatile("st.release.gpu.u32 [%0], %1;" :: "l"(p), "r"(v) : "memory");
}
__device__ __forceinline__ int ld_acquire_gpu(const int* p) {
    int v;
    asm volatile("ld.acquire.gpu.u32 %0, [%1];" : "=r"(v) : "l"(p) : "memory");
    return v;
}

// ---------------------------------------------------------------------------
// 3xTF32 tensor-core projection GEMM (near-fp32 accuracy), double-buffered.
// out[m][n] = sum_k A[m][k] * W[n][k] + b1[n] + b2[n]
// v = hi + lo (hi = tf32-rounded); C += hi*hi + hi*lo + lo*hi.
// CTA tile: M=128, N=64, K chunked by 32. 8 warps, each 32x32 (2x2 wmma).
// FIRST: A = x [B,T,I], out = g_xw0.  else: A = g_h rows m, out = g_xw1.
// WAIT: gate on layer-0 scan flags (h[2by], h[2by+1] complete) -- enables
// PDL overlap with the layer-0 scan. Poll: 1 warp, nanosleep backoff.
// ---------------------------------------------------------------------------
#define LDA 36                       // 32 + 4 skew (16B-aligned rows)
#define A_FL (128 * LDA)
#define B_FL (64 * LDA)
#define BUF_FL (2 * (A_FL + B_FL))   // 13824 floats per buffer
#define TOT_FL (2 * BUF_FL)          // 110592 B
#define LDC 72

template<int KD, bool FIRST, bool WAIT>
__global__ __launch_bounds__(256, 2) void proj_tc(
    const float* __restrict__ xin, const float* __restrict__ W,
    const float* __restrict__ b1,  const float* __restrict__ b2)
{
    extern __shared__ float s[];
    __shared__ float biasS[64];

    const float* __restrict__ A = FIRST ? xin : (const float*)g_h;
    float* __restrict__ outp = FIRST ? g_xw0 : g_xw1;
    const int tid = threadIdx.x;
    const int wid = tid >> 5;
    const int lane = tid & 31;
    const int n0 = blockIdx.x * 64;
    const int m0 = blockIdx.y * 128;
    const int wm = wid & 3;
    const int wn = wid >> 2;

    if (WAIT) {
        // Need h rows for t = 2by and 2by+1: all 128 (bblk,jblk) flags >= 2by+2
        if (wid == 0) {
            const int target = 2 * (int)blockIdx.y + 2;
            for (;;) {
                int ok = 1;
                #pragma unroll
                for (int q = 0; q < 4; q++) {
                    int idx = lane + q * 32;                // 0..127
                    int v = ld_acquire_gpu(&g_flag[0][idx >> 4][idx & 15][0]);
                    ok &= (v >= target);
                }
                if (__all_sync(0xffffffffu, ok)) break;
                __nanosleep(256);
            }
        }
        __syncthreads();
    }

    if (tid < 64) biasS[tid] = b1[n0 + tid] + b2[n0 + tid];

    int a_row[4], a_col[4];
    #pragma unroll
    for (int i = 0; i < 4; i++) {
        int idx = tid + i * 256;
        a_row[i] = idx >> 3;
        a_col[i] = (idx & 7) * 4;
    }
    int b_row[2], b_col[2];
    #pragma unroll
    for (int i = 0; i < 2; i++) {
        int idx = tid + i * 256;
        b_row[i] = idx >> 3;
        b_col[i] = (idx & 7) * 4;
    }

    size_t a_off[4];
    #pragma unroll
    for (int i = 0; i < 4; i++) {
        int m = m0 + a_row[i];
        a_off[i] = FIRST ? ((size_t)(m & 63) * Tdim + (m >> 6)) * KD
                         : (size_t)m * KD;
    }
    size_t b_off[2];
    #pragma unroll
    for (int i = 0; i < 2; i++)
        b_off[i] = (size_t)(n0 + b_row[i]) * KD;

    wmma::fragment<wmma::accumulator, 16, 16, 8, float> cf[2][2];
    #pragma unroll
    for (int i = 0; i < 2; i++)
        #pragma unroll
        for (int j = 0; j < 2; j++)
            wmma::fill_fragment(cf[i][j], 0.0f);

    float4 pa[4], pb[2];

    auto stage = [&](float* base) {
        float* Ah = base;
        float* Al = base + A_FL;
        float* Bh = base + 2 * A_FL;
        float* Bl = base + 2 * A_FL + B_FL;
        #pragma unroll
        for (int i = 0; i < 4; i++) {
            int o = a_row[i] * LDA + a_col[i];
            float hx = wmma::__float_to_tf32(pa[i].x);
            float hy = wmma::__float_to_tf32(pa[i].y);
            float hz = wmma::__float_to_tf32(pa[i].z);
            float hw = wmma::__float_to_tf32(pa[i].w);
            Ah[o+0] = hx; Ah[o+1] = hy; Ah[o+2] = hz; Ah[o+3] = hw;
            Al[o+0] = pa[i].x - hx; Al[o+1] = pa[i].y - hy;
            Al[o+2] = pa[i].z - hz; Al[o+3] = pa[i].w - hw;
        }
        #pragma unroll
        for (int i = 0; i < 2; i++) {
            int o = b_row[i] * LDA + b_col[i];
            float hx = wmma::__float_to_tf32(pb[i].x);
            float hy = wmma::__float_to_tf32(pb[i].y);
            float hz = wmma::__float_to_tf32(pb[i].z);
            float hw = wmma::__float_to_tf32(pb[i].w);
            Bh[o+0] = hx; Bh[o+1] = hy; Bh[o+2] = hz; Bh[o+3] = hw;
            Bl[o+0] = pb[i].x - hx; Bl[o+1] = pb[i].y - hy;
            Bl[o+2] = pb[i].z - hz; Bl[o+3] = pb[i].w - hw;
        }
    };
    auto gload = [&](int kt) {
        int k0 = kt * 32;
        #pragma unroll
        for (int i = 0; i < 4; i++)
            pa[i] = *reinterpret_cast<const float4*>(A + a_off[i] + k0 + a_col[i]);
        #pragma unroll
        for (int i = 0; i < 2; i++)
            pb[i] = *reinterpret_cast<const float4*>(W + b_off[i] + k0 + b_col[i]);
    };

    const int KT = KD / 32;
    gload(0);
    stage(s);
    if (KT > 1) gload(1);
    __syncthreads();

    for (int kt = 0; kt < KT; ++kt) {
        float* cur = s + (kt & 1) * BUF_FL;
        if (kt + 1 < KT) stage(s + ((kt + 1) & 1) * BUF_FL);

        const float* Ah = cur;
        const float* Al = cur + A_FL;
        const float* Bh = cur + 2 * A_FL;
        const float* Bl = cur + 2 * A_FL + B_FL;
        #pragma unroll
        for (int kk = 0; kk < 32; kk += 8) {
            wmma::fragment<wmma::matrix_a, 16, 16, 8, wmma::precision::tf32, wmma::row_major> ah[2], al[2];
            wmma::fragment<wmma::matrix_b, 16, 16, 8, wmma::precision::tf32, wmma::col_major> bh[2], bl[2];
            #pragma unroll
            for (int i = 0; i < 2; i++) {
                wmma::load_matrix_sync(ah[i], Ah + (wm * 32 + i * 16) * LDA + kk, LDA);
                wmma::load_matrix_sync(al[i], Al + (wm * 32 + i * 16) * LDA + kk, LDA);
            }
            #pragma unroll
            for (int j = 0; j < 2; j++) {
                wmma::load_matrix_sync(bh[j], Bh + (wn * 32 + j * 16) * LDA + kk, LDA);
                wmma::load_matrix_sync(bl[j], Bl + (wn * 32 + j * 16) * LDA + kk, LDA);
            }
            #pragma unroll
            for (int i = 0; i < 2; i++)
                #pragma unroll
                for (int j = 0; j < 2; j++) {
                    wmma::mma_sync(cf[i][j], al[i], bh[j], cf[i][j]);
                    wmma::mma_sync(cf[i][j], ah[i], bl[j], cf[i][j]);
                    wmma::mma_sync(cf[i][j], ah[i], bh[j], cf[i][j]);
                }
        }
        if (kt + 2 < KT) gload(kt + 2);
        __syncthreads();
    }

    #pragma unroll
    for (int i = 0; i < 2; i++)
        #pragma unroll
        for (int j = 0; j < 2; j++)
            wmma::store_matrix_sync(s + (wm * 32 + i * 16) * LDC + wn * 32 + j * 16,
                                    cf[i][j], LDC, wmma::mem_row_major);
    __syncthreads();

    #pragma unroll
    for (int i = 0; i < 8; i++) {
        int idx = tid + i * 256;
        int row = idx >> 4;
        int col = (idx & 15) * 4;
        float4 o;
        o.x = s[row * LDC + col + 0] + biasS[col + 0];
        o.y = s[row * LDC + col + 1] + biasS[col + 1];
        o.z = s[row * LDC + col + 2] + biasS[col + 2];
        o.w = s[row * LDC + col + 3] + biasS[col + 3];
        *reinterpret_cast<float4*>(&outp[(size_t)(m0 + row) * Hdim + n0 + col]) = o;
    }
}

// ---------------------------------------------------------------------------
// Recurrent scan (R8 design): h[t] = relu(xw[t] + h[t-1] @ Whh^T).
// Grid (16 j-blocks, 8 b-blocks) = 128 CTAs, 256 threads each.
// Triggers programmatic launch completion at entry so a PDL successor
// (the layer-1 projection) can come up and overlap via the step flags.
// ---------------------------------------------------------------------------
__global__ __launch_bounds__(256) void rnn_scan(const float* __restrict__ Whh, int layer)
{
    if (threadIdx.x == 0) cudaTriggerProgrammaticLaunchCompletion();

    __shared__ __align__(16) float hs[8 * 512];
    __shared__ __align__(16) float part[8 * 8 * 32];

    const int tid  = threadIdx.x;
    const int w    = tid >> 5;
    const int lane = tid & 31;
    const int jblk = blockIdx.x;
    const int bblk = blockIdx.y;
    const int j = jblk * 32 + lane;
    const int rowbase = bblk * 8;
    const float* __restrict__ xw = layer ? g_xw1 : g_xw0;
    int* myflag = &g_flag[layer][bblk][jblk][0];
    const int* pf = (lane < 2) ? &g_flag[layer][bblk][2 * w + lane][0] : nullptr;

    float4 wv[16];
    const float4* Wr = reinterpret_cast<const float4*>(Whh + (size_t)j * Hdim + w * 64);
    #pragma unroll
    for (int i = 0; i < 16; i++) wv[i] = Wr[i];

    float4* hs4 = reinterpret_cast<float4*>(hs);
    const int b2 = tid >> 5, j2 = tid & 31;
    const size_t outbase = (size_t)(rowbase + b2) * Hdim + jblk * 32 + j2;

    int l_b[4], l_q[4];
    #pragma unroll
    for (int i = 0; i < 4; i++) {
        int idx = lane + i * 32;
        l_b[i] = idx >> 4;
        l_q[i] = idx & 15;
    }

    for (int t = 0; t < Tdim; ++t) {
        const size_t off = (size_t)t * BH + outbase;
        float xv = __ldcg(&xw[off]);

        if (t > 0) {
            for (;;) {
                int v = (lane < 2) ? ld_acquire_gpu(pf) : 0x7fffffff;
                if (__all_sync(0xffffffffu, v >= t)) break;
            }
            const float4* src = reinterpret_cast<const float4*>(
                g_h + (size_t)(t - 1) * BH + (size_t)rowbase * Hdim);
            #pragma unroll
            for (int i = 0; i < 4; i++)
                hs4[l_b[i] * 128 + w * 16 + l_q[i]] =
                    __ldcg(&src[l_b[i] * 128 + w * 16 + l_q[i]]);
        } else {
            float4 z = make_float4(0.f, 0.f, 0.f, 0.f);
            #pragma unroll
            for (int i = 0; i < 4; i++)
                hs4[l_b[i] * 128 + w * 16 + l_q[i]] = z;
        }
        __syncwarp();

        float acc[8];
        #pragma unroll
        for (int b = 0; b < 8; b++) acc[b] = 0.f;
        #pragma unroll
        for (int i = 0; i < 16; i++) {
            float4 w4 = wv[i];
            #pragma unroll
            for (int b = 0; b < 8; b++) {
                float4 h4 = hs4[b * 128 + w * 16 + i];
                acc[b] = fmaf(h4.w, w4.w,
                          fmaf(h4.z, w4.z,
                           fmaf(h4.y, w4.y,
                            fmaf(h4.x, w4.x, acc[b]))));
            }
        }
        #pragma unroll
        for (int b = 0; b < 8; b++)
            part[(w * 8 + b) * 32 + lane] = acc[b];
        __syncthreads();

        {
            float s2 = 0.f;
            #pragma unroll
            for (int ww = 0; ww < 8; ww++)
                s2 += part[(ww * 8 + b2) * 32 + j2];
            g_h[off] = fmaxf(xv + s2, 0.f);
        }
        __syncthreads();
        if (tid == 0) st_release_gpu(myflag, t + 1);
    }
}

// ---------------------------------------------------------------------------
// FC + sigmoid: out[b*T + t] = sigmoid(dot(h1[t][b], W_fc) + b_fc)
// ---------------------------------------------------------------------------
__global__ __launch_bounds__(256) void fc_sigmoid(
    const float* __restrict__ wfc, const float* __restrict__ bfc,
    float* __restrict__ out)
{
    int gw   = (blockIdx.x * blockDim.x + threadIdx.x) >> 5;
    int lane = threadIdx.x & 31;
    int t = gw >> 6, b = gw & 63;

    const float4* hp = reinterpret_cast<const float4*>(g_h + (size_t)gw * Hdim);
    const float4* wp = reinterpret_cast<const float4*>(wfc);
    float s = 0.f;
    #pragma unroll
    for (int r = 0; r < 4; r++) {
        float4 hv = hp[lane + r * 32];
        float4 wv = wp[lane + r * 32];
        s += hv.x * wv.x + hv.y * wv.y + hv.z * wv.z + hv.w * wv.w;
    }
    #pragma unroll
    for (int o = 16; o > 0; o >>= 1)
        s += __shfl_xor_sync(0xffffffffu, s, o);
    if (lane == 0) {
        float v = s + bfc[0];
        out[(size_t)b * Tdim + t] = 1.f / (1.f + expf(-v));
    }
}

// ---------------------------------------------------------------------------
extern "C" void kernel_launch(void* const* d_in, const int* in_sizes, int n_in,
                              void* d_out, int out_size)
{
    (void)in_sizes; (void)n_in; (void)out_size;
    const float* x    = (const float*)d_in[0];
    const float* Wih0 = (const float*)d_in[1];
    const float* Whh0 = (const float*)d_in[2];
    const float* bih0 = (const float*)d_in[3];
    const float* bhh0 = (const float*)d_in[4];
    const float* Wih1 = (const float*)d_in[5];
    const float* Whh1 = (const float*)d_in[6];
    const float* bih1 = (const float*)d_in[7];
    const float* bhh1 = (const float*)d_in[8];
    const float* Wfc  = (const float*)d_in[9];
    const float* bfc  = (const float*)d_in[10];
    float* out = (float*)d_out;

    const int dyn_smem = TOT_FL * sizeof(float);  // 110592 B
    static bool attr_set = false;
    if (!attr_set) {
        cudaFuncSetAttribute(proj_tc<Idim, true, false>,
                             cudaFuncAttributeMaxDynamicSharedMemorySize, dyn_smem);
        cudaFuncSetAttribute(proj_tc<Hdim, false, true>,
                             cudaFuncAttributeMaxDynamicSharedMemorySize, dyn_smem);
        attr_set = true;
    }

    dim3 gemm_grid(8, 256);
    dim3 scan_grid(16, 8);

    zero_flags_k<<<32, 512>>>();

    // Layer 0
    proj_tc<Idim, true, false><<<gemm_grid, 256, dyn_smem>>>(x, Wih0, bih0, bhh0);
    rnn_scan<<<scan_grid, 256>>>(Whh0, 0);

    // Layer-1 projection: PDL-overlapped with the layer-0 scan.
    // Gate correctness comes from the in-kernel flag wait (WAIT=true), which
    // also makes the plain-serialized fallback correct (polls pass instantly).
    static int pdl_ok = -1;   // -1 unknown, 1 works, 0 fall back
    bool launched = false;
    if (pdl_ok != 0) {
        cudaLaunchConfig_t cfg = {};
        cfg.gridDim = gemm_grid;
        cfg.blockDim = dim3(256, 1, 1);
        cfg.dynamicSmemBytes = dyn_smem;
        cfg.stream = 0;
        cudaLaunchAttribute at[1];
        at[0].id = cudaLaunchAttributeProgrammaticStreamSerialization;
        at[0].val.programmaticStreamSerializationAllowed = 1;
        cfg.attrs = at;
        cfg.numAttrs = 1;
        cudaError_t e = cudaLaunchKernelEx(&cfg, proj_tc<Hdim, false, true>,
                                           x, Wih1, bih1, bhh1);
        if (e == cudaSuccess) { pdl_ok = 1; launched = true; }
        else { (void)cudaGetLastError(); pdl_ok = 0; }
    }
    if (!launched)
        proj_tc<Hdim, false, true><<<gemm_grid, 256, dyn_smem>>>(x, Wih1, bih1, bhh1);

    // Layer 1 scan (waits for proj1 + scan0 via stream order)
    rnn_scan<<<scan_grid, 256>>>(Whh1, 1);

    // Head
    fc_sigmoid<<<4096, 256>>>(Wfc, bfc, out);
}